// round 6
// baseline (speedup 1.0000x reference)
#include <cuda_runtime.h>
#include <math.h>
#include <stdint.h>

// ---------------------------------------------------------------------------
// VDP attention, round 4: 512-thread (16-warp) tf32 mma.sync GEMMs to fix
// warp starvation (2 -> 4 warps/SMSP). 32x32 warp tiles keep regs low.
// B=4, N=1024, D=1024, H=16, Dh=64.
// ---------------------------------------------------------------------------

#define B_ 4
#define N_ 1024
#define D_ 1024
#define H_ 16
#define DH_ 64
#define M_ (B_ * N_)       /* 4096 rows */
#define QKV_ (3 * D_)      /* 3072 */
#define BH_ (B_ * H_)      /* 64 */
#define SCALE_ 0.125f      /* 64^-0.5 */

// ------------------------- scratch (static device) -------------------------
__device__ float g_mu_n [M_ * D_];
__device__ float g_sg_n [M_ * D_];
__device__ float g_m2s  [M_ * D_];          // mu_n^2 + sigma_n
__device__ float g_Wqkv_mu_r[QKV_ * D_];    // tf32-rounded copies
__device__ float g_Wqkv_sig[QKV_ * D_];
__device__ float g_Wqkv_mu2[QKV_ * D_];
__device__ float g_Wout_mu_r[D_ * D_];
__device__ float g_Wout_sig[D_ * D_];
__device__ float g_Wout_mu2[D_ * D_];
__device__ float g_mu_qkv[M_ * QKV_];
__device__ float g_sg_qkv[M_ * QKV_];
__device__ float g_mu_dots[BH_ * N_ * N_];  // becomes attn in place
__device__ float g_sg_dots[BH_ * N_ * N_];
__device__ float g_mu_o [M_ * D_];
__device__ float g_sg_o [M_ * D_];
__device__ float g_m2s_o[M_ * D_];          // mu_o^2 + sg_o

// ------------------------------ tf32 helpers -------------------------------
__device__ __forceinline__ uint32_t f2tf32(float f) {
    uint32_t u;
    asm("cvt.rna.tf32.f32 %0, %1;" : "=r"(u) : "f"(f));
    return u;
}
__device__ __forceinline__ float rtf(float f) {
    return __uint_as_float(f2tf32(f));
}

__device__ __forceinline__ void mma_tf32(float c[4], const uint32_t a[4],
                                         const uint32_t b[2]) {
    asm volatile(
        "mma.sync.aligned.m16n8k8.row.col.f32.tf32.tf32.f32 "
        "{%0,%1,%2,%3},{%4,%5,%6,%7},{%8,%9},{%0,%1,%2,%3};"
        : "+f"(c[0]), "+f"(c[1]), "+f"(c[2]), "+f"(c[3])
        : "r"(a[0]), "r"(a[1]), "r"(a[2]), "r"(a[3]), "r"(b[0]), "r"(b[1]));
}

__device__ __forceinline__ void cp16(void* smem_ptr, const void* g) {
    uint32_t s = (uint32_t)__cvta_generic_to_shared(smem_ptr);
    asm volatile("cp.async.cg.shared.global [%0], [%1], 16;\n" :: "r"(s), "l"(g));
}
__device__ __forceinline__ void cp_commit() {
    asm volatile("cp.async.commit_group;\n");
}
template <int N>
__device__ __forceinline__ void cp_wait() {
    asm volatile("cp.async.wait_group %0;\n" :: "n"(N));
}

// ------------------------- pipelined tensor-core GEMM ----------------------
// C[M,N] (+)= scale * A[M,K] * op(B).  op(B)=B[N,K] (BT=false) or B[K,N]
// (BT=true).  BK=32, 3-stage cp.async pipeline, THR threads, warps WR x WC.
// Inputs assumed pre-rounded to tf32; MMA consumes raw bits.
template <int THR, int BM, int BN, int WR, int WC, bool ACCUM, bool BT, bool RND>
__device__ __forceinline__ void gemm_core(float* __restrict__ C,
                                          const float* __restrict__ A,
                                          const float* __restrict__ Bm,
                                          int K, int lda, int ldb, int ldc,
                                          float scale) {
    constexpr int WM = BM / WR, WN = BN / WC;
    constexpr int MT = WM / 16, NT = WN / 8;
    constexpr int PA = 36;                  // A smem pitch (k-contig rows)
    constexpr int PB = BT ? 72 : 36;        // B pitch (k-major when BT)
    constexpr int ASZ = BM * PA;
    constexpr int BSZ = BT ? 32 * PB : BN * PB;
    constexpr int STG = ASZ + BSZ;
    constexpr int NA = BM * 32 / (THR * 4); // float4 cp.async per thread (A)
    constexpr int NB = BN * 32 / (THR * 4);

    extern __shared__ uint32_t sh[];

    const int tid = threadIdx.x;
    const int bm = blockIdx.y * BM, bn = blockIdx.x * BN;
    const int w = tid >> 5, lane = tid & 31;
    const int gr = lane >> 2, tc = lane & 3;
    const int wm = (w / WC) * WM, wn = (w % WC) * WN;
    const int niter = K / 32;

    auto load_stage = [&](int s, int k0) {
        uint32_t* As = sh + s * STG;
        uint32_t* Bs = As + ASZ;
        #pragma unroll
        for (int r = 0; r < NA; r++) {
            int idx = tid + THR * r;
            cp16(&As[(idx >> 3) * PA + (idx & 7) * 4],
                 A + (size_t)(bm + (idx >> 3)) * lda + (idx & 7) * 4 + k0);
        }
        #pragma unroll
        for (int r = 0; r < NB; r++) {
            int idx = tid + THR * r;
            if (BT) {
                int kr = idx / (BN / 4), n0 = (idx % (BN / 4)) * 4;
                cp16(&Bs[kr * PB + n0],
                     Bm + (size_t)(k0 + kr) * ldb + bn + n0);
            } else {
                cp16(&Bs[(idx >> 3) * PB + (idx & 7) * 4],
                     Bm + (size_t)(bn + (idx >> 3)) * ldb + (idx & 7) * 4 + k0);
            }
        }
    };

    float acc[MT][NT][4] = {};

    load_stage(0, 0);
    cp_commit();
    if (niter > 1) load_stage(1, 32);
    cp_commit();

    for (int i = 0; i < niter; i++) {
        cp_wait<1>();
        __syncthreads();
        if (i + 2 < niter) load_stage((i + 2) % 3, (i + 2) * 32);
        cp_commit();

        const uint32_t* As = sh + (i % 3) * STG;
        const uint32_t* Bs = As + ASZ;
        #pragma unroll
        for (int g = 0; g < 4; g++) {
            uint32_t af[MT][4], bf[NT][2];
            #pragma unroll
            for (int ii = 0; ii < MT; ii++) {
                int base = (wm + ii * 16 + gr) * PA + g * 8 + tc;
                af[ii][0] = As[base];
                af[ii][2] = As[base + 4];
                af[ii][1] = As[base + 8 * PA];
                af[ii][3] = As[base + 8 * PA + 4];
            }
            #pragma unroll
            for (int j = 0; j < NT; j++) {
                if (BT) {
                    int n = wn + j * 8 + gr;
                    bf[j][0] = Bs[(g * 8 + tc) * PB + n];
                    bf[j][1] = Bs[(g * 8 + tc + 4) * PB + n];
                } else {
                    int base = (wn + j * 8 + gr) * PB + g * 8 + tc;
                    bf[j][0] = Bs[base];
                    bf[j][1] = Bs[base + 4];
                }
            }
            #pragma unroll
            for (int ii = 0; ii < MT; ii++)
                #pragma unroll
                for (int j = 0; j < NT; j++)
                    mma_tf32(acc[ii][j], af[ii], bf[j]);
        }
        __syncthreads();
    }

    // ---- epilogue ----
    #pragma unroll
    for (int ii = 0; ii < MT; ii++) {
        #pragma unroll
        for (int j = 0; j < NT; j++) {
            int row0 = bm + wm + ii * 16 + gr;
            int col  = bn + wn + j * 8 + 2 * tc;
            float* p0 = C + (size_t)row0 * ldc + col;
            float* p1 = C + (size_t)(row0 + 8) * ldc + col;
            float2 v0 = make_float2(acc[ii][j][0] * scale, acc[ii][j][1] * scale);
            float2 v1 = make_float2(acc[ii][j][2] * scale, acc[ii][j][3] * scale);
            if (ACCUM) {
                float2 o0 = *(const float2*)p0, o1 = *(const float2*)p1;
                v0.x += o0.x; v0.y += o0.y; v1.x += o1.x; v1.y += o1.y;
            }
            if (RND) {
                v0.x = rtf(v0.x); v0.y = rtf(v0.y);
                v1.x = rtf(v1.x); v1.y = rtf(v1.y);
            }
            *(float2*)p0 = v0;
            *(float2*)p1 = v1;
        }
    }
}

// ---------------------------- kernel wrappers ------------------------------
// 512 threads, 16 warps (4x4), 32x32 warp tiles: low regs, 4 warps/SMSP.
template <bool ACCUM, bool RND>
__global__ void __launch_bounds__(512, 1)
gemm_tc_kernel(float* __restrict__ C, const float* __restrict__ A,
               const float* __restrict__ B, int K, int lda, int ldb, int ldc) {
    gemm_core<512, 128, 128, 4, 4, ACCUM, false, RND>(C, A, B, K, lda, ldb, ldc, 1.0f);
}

__global__ void __launch_bounds__(512, 1)
dots_tc_kernel() {
    const int z = blockIdx.z;
    const float* qkv = (z >= BH_) ? g_sg_qkv : g_mu_qkv;
    float* dots      = (z >= BH_) ? g_sg_dots : g_mu_dots;
    const int bh = z & (BH_ - 1);
    const int b = bh >> 4, h = bh & 15;
    const float* A  = qkv + (size_t)b * N_ * QKV_ + h * DH_;
    const float* Bq = A + D_;
    float* C = dots + (size_t)bh * N_ * N_;
    gemm_core<512, 128, 128, 4, 4, false, false, false>(C, A, Bq, DH_, QKV_, QKV_, N_, SCALE_);
}

__global__ void __launch_bounds__(256, 1)
pv_tc_kernel() {
    const int z = blockIdx.z;
    const float* attn = (z >= BH_) ? g_sg_dots : g_mu_dots;
    const float* qkv  = (z >= BH_) ? g_sg_qkv : g_mu_qkv;
    float* O          = (z >= BH_) ? g_sg_o : g_mu_o;
    const int bh = z & (BH_ - 1);
    const int b = bh >> 4, h = bh & 15;
    const float* A = attn + (size_t)bh * N_ * N_;
    const float* V = qkv + (size_t)b * N_ * QKV_ + 2 * D_ + h * DH_;
    float* C = O + (size_t)b * N_ * D_ + h * DH_;
    gemm_core<256, 128, 64, 4, 2, false, true, true>(C, A, V, N_, N_, QKV_, D_, 1.0f);
}

// ------------------------------ prep weights -------------------------------
__device__ __forceinline__ float softplusf(float x) {
    return fmaxf(x, 0.0f) + log1pf(expf(-fabsf(x)));
}

__global__ void prep_weights_kernel(const float* __restrict__ Wqkv_mu,
                                    const float* __restrict__ Wqkv_raw,
                                    const float* __restrict__ Wout_mu,
                                    const float* __restrict__ Wout_raw) {
    int i = blockIdx.x * blockDim.x + threadIdx.x;
    const int nq = QKV_ * D_;
    if (i < nq) {
        float w = Wqkv_mu[i];
        g_Wqkv_mu_r[i] = rtf(w);
        g_Wqkv_mu2[i] = rtf(w * w);
        g_Wqkv_sig[i] = rtf(softplusf(Wqkv_raw[i]));
    } else {
        int j = i - nq;
        if (j < D_ * D_) {
            float w = Wout_mu[j];
            g_Wout_mu_r[j] = rtf(w);
            g_Wout_mu2[j] = rtf(w * w);
            g_Wout_sig[j] = rtf(softplusf(Wout_raw[j]));
        }
    }
}

// -------------------------------- layernorm --------------------------------
__global__ void layernorm_kernel(const float* __restrict__ mu,
                                 const float* __restrict__ sigma,
                                 const float* __restrict__ gamma,
                                 const float* __restrict__ beta) {
    const int row = blockIdx.x;
    const int t   = threadIdx.x;
    const float4* mrow = (const float4*)(mu + (size_t)row * D_);
    float4 m = mrow[t];

    float s  = m.x + m.y + m.z + m.w;
    float sq = m.x * m.x + m.y * m.y + m.z * m.z + m.w * m.w;

    __shared__ float red[256];
    red[t] = s; __syncthreads();
    #pragma unroll
    for (int o = 128; o > 0; o >>= 1) { if (t < o) red[t] += red[t + o]; __syncthreads(); }
    float mean = red[0] * (1.0f / D_);
    __syncthreads();
    red[t] = sq; __syncthreads();
    #pragma unroll
    for (int o = 128; o > 0; o >>= 1) { if (t < o) red[t] += red[t + o]; __syncthreads(); }
    float var = red[0] * (1.0f / D_) - mean * mean;
    float inv = rsqrtf(var + 1e-5f);

    const float4 sg = ((const float4*)(sigma + (size_t)row * D_))[t];
    const float4 gm = ((const float4*)gamma)[t];
    const float4 bt = ((const float4*)beta)[t];

    float4 mo, so, m2;
    mo.x = (m.x - mean) * inv * gm.x + bt.x;  so.x = sg.x * gm.x * gm.x * inv * inv;  m2.x = fmaf(mo.x, mo.x, so.x);
    mo.y = (m.y - mean) * inv * gm.y + bt.y;  so.y = sg.y * gm.y * gm.y * inv * inv;  m2.y = fmaf(mo.y, mo.y, so.y);
    mo.z = (m.z - mean) * inv * gm.z + bt.z;  so.z = sg.z * gm.z * gm.z * inv * inv;  m2.z = fmaf(mo.z, mo.z, so.z);
    mo.w = (m.w - mean) * inv * gm.w + bt.w;  so.w = sg.w * gm.w * gm.w * inv * inv;  m2.w = fmaf(mo.w, mo.w, so.w);

    mo.x = rtf(mo.x); mo.y = rtf(mo.y); mo.z = rtf(mo.z); mo.w = rtf(mo.w);
    so.x = rtf(so.x); so.y = rtf(so.y); so.z = rtf(so.z); so.w = rtf(so.w);
    m2.x = rtf(m2.x); m2.y = rtf(m2.y); m2.z = rtf(m2.z); m2.w = rtf(m2.w);

    ((float4*)g_mu_n)[(size_t)row * 256 + t] = mo;
    ((float4*)g_sg_n)[(size_t)row * 256 + t] = so;
    ((float4*)g_m2s )[(size_t)row * 256 + t] = m2;
}

// --------------------------------- softmax ---------------------------------
__global__ void softmax_kernel() {
    const size_t row = blockIdx.x;
    float* mrow = g_mu_dots + row * N_;
    float* srow = g_sg_dots + row * N_;
    const int t = threadIdx.x;

    float4 m = ((const float4*)mrow)[t];
    float lm = fmaxf(fmaxf(m.x, m.y), fmaxf(m.z, m.w));

    __shared__ float red[256];
    red[t] = lm; __syncthreads();
    #pragma unroll
    for (int o = 128; o > 0; o >>= 1) { if (t < o) red[t] = fmaxf(red[t], red[t + o]); __syncthreads(); }
    const float rmax = red[0];
    __syncthreads();

    float4 e;
    e.x = __expf(m.x - rmax); e.y = __expf(m.y - rmax);
    e.z = __expf(m.z - rmax); e.w = __expf(m.w - rmax);
    red[t] = e.x + e.y + e.z + e.w; __syncthreads();
    #pragma unroll
    for (int o = 128; o > 0; o >>= 1) { if (t < o) red[t] += red[t + o]; __syncthreads(); }
    const float inv = 1.0f / red[0];

    float4 p;
    p.x = e.x * inv; p.y = e.y * inv; p.z = e.z * inv; p.w = e.w * inv;

    float4 sg = ((const float4*)srow)[t];
    float4 so;
    float jx = p.x * (1.0f - p.x); so.x = rtf(jx * jx * sg.x);
    float jy = p.y * (1.0f - p.y); so.y = rtf(jy * jy * sg.y);
    float jz = p.z * (1.0f - p.z); so.z = rtf(jz * jz * sg.z);
    float jw = p.w * (1.0f - p.w); so.w = rtf(jw * jw * sg.w);
    p.x = rtf(p.x); p.y = rtf(p.y); p.z = rtf(p.z); p.w = rtf(p.w);

    ((float4*)mrow)[t] = p;
    ((float4*)srow)[t] = so;
}

// ------------------------------ m2s for output -----------------------------
__global__ void m2so_kernel() {
    int i = blockIdx.x * blockDim.x + threadIdx.x;
    float mo = g_mu_o[i];
    g_m2s_o[i] = rtf(fmaf(mo, mo, g_sg_o[i]));
}

// --------------------------------- launch ----------------------------------
extern "C" void kernel_launch(void* const* d_in, const int* in_sizes, int n_in,
                              void* d_out, int out_size) {
    (void)in_sizes; (void)n_in; (void)out_size;
    const float* mu       = (const float*)d_in[0];
    const float* sigma    = (const float*)d_in[1];
    const float* gamma    = (const float*)d_in[2];
    const float* beta     = (const float*)d_in[3];
    const float* Wqkv_mu  = (const float*)d_in[4];
    const float* Wqkv_raw = (const float*)d_in[5];
    const float* Wout_mu  = (const float*)d_in[6];
    const float* Wout_raw = (const float*)d_in[7];
    float* out = (float*)d_out;

    float *p_mu_n, *p_sg_n, *p_m2s, *p_wq_r, *p_wqs, *p_wq2, *p_wo_r, *p_wos, *p_wo2;
    float *p_mu_qkv, *p_sg_qkv, *p_mu_o, *p_sg_o, *p_m2so;
    cudaGetSymbolAddress((void**)&p_mu_n,   g_mu_n);
    cudaGetSymbolAddress((void**)&p_sg_n,   g_sg_n);
    cudaGetSymbolAddress((void**)&p_m2s,    g_m2s);
    cudaGetSymbolAddress((void**)&p_wq_r,   g_Wqkv_mu_r);
    cudaGetSymbolAddress((void**)&p_wqs,    g_Wqkv_sig);
    cudaGetSymbolAddress((void**)&p_wq2,    g_Wqkv_mu2);
    cudaGetSymbolAddress((void**)&p_wo_r,   g_Wout_mu_r);
    cudaGetSymbolAddress((void**)&p_wos,    g_Wout_sig);
    cudaGetSymbolAddress((void**)&p_wo2,    g_Wout_mu2);
    cudaGetSymbolAddress((void**)&p_mu_qkv, g_mu_qkv);
    cudaGetSymbolAddress((void**)&p_sg_qkv, g_sg_qkv);
    cudaGetSymbolAddress((void**)&p_mu_o,   g_mu_o);
    cudaGetSymbolAddress((void**)&p_sg_o,   g_sg_o);
    cudaGetSymbolAddress((void**)&p_m2so,   g_m2s_o);

    const int SMEM_BIG = 3 * (128 * 36 + 128 * 36) * 4;   // 110592
    const int SMEM_PV  = 3 * (128 * 36 + 32 * 72) * 4;    // 82944
    cudaFuncSetAttribute(gemm_tc_kernel<false, true>,  cudaFuncAttributeMaxDynamicSharedMemorySize, SMEM_BIG);
    cudaFuncSetAttribute(gemm_tc_kernel<true,  true>,  cudaFuncAttributeMaxDynamicSharedMemorySize, SMEM_BIG);
    cudaFuncSetAttribute(gemm_tc_kernel<false, false>, cudaFuncAttributeMaxDynamicSharedMemorySize, SMEM_BIG);
    cudaFuncSetAttribute(gemm_tc_kernel<true,  false>, cudaFuncAttributeMaxDynamicSharedMemorySize, SMEM_BIG);
    cudaFuncSetAttribute(dots_tc_kernel, cudaFuncAttributeMaxDynamicSharedMemorySize, SMEM_BIG);
    cudaFuncSetAttribute(pv_tc_kernel,   cudaFuncAttributeMaxDynamicSharedMemorySize, SMEM_PV);

    // 1. weight transforms (+ tf32 rounding)
    prep_weights_kernel<<<(QKV_ * D_ + D_ * D_ + 255) / 256, 256>>>(
        Wqkv_mu, Wqkv_raw, Wout_mu, Wout_raw);

    // 2. layernorm (+ mu^2+sigma, tf32 rounded)
    layernorm_kernel<<<M_, 256>>>(mu, sigma, gamma, beta);

    // 3. QKV projections (pipelined tensor cores, 512 thr)
    dim3 gq(QKV_ / 128, M_ / 128);
    gemm_tc_kernel<false, true><<<gq, 512, SMEM_BIG>>>(p_mu_qkv, p_mu_n, p_wq_r, D_, D_, D_, QKV_);
    gemm_tc_kernel<false, true><<<gq, 512, SMEM_BIG>>>(p_sg_qkv, p_m2s,  p_wqs,  D_, D_, D_, QKV_);
    gemm_tc_kernel<true,  true><<<gq, 512, SMEM_BIG>>>(p_sg_qkv, p_sg_n, p_wq2,  D_, D_, D_, QKV_);

    // 4. attention scores (mu & sg), scaled
    dots_tc_kernel<<<dim3(N_ / 128, N_ / 128, 2 * BH_), 512, SMEM_BIG>>>();

    // 5. softmax + variance Jacobian (in place, tf32 rounded)
    softmax_kernel<<<BH_ * N_, 256>>>();

    // 6. attn @ V (mu & sg)
    pv_tc_kernel<<<dim3(1, N_ / 128, 2 * BH_), 256, SMEM_PV>>>();

    // 7. mu_o^2 + sg_o
    m2so_kernel<<<(M_ * D_) / 256, 256>>>();

    // 8. output projection -> d_out (no rounding on final results)
    dim3 go(D_ / 128, M_ / 128);
    gemm_tc_kernel<false, false><<<go, 512, SMEM_BIG>>>(out,           p_mu_o, p_wo_r, D_, D_, D_, D_);
    gemm_tc_kernel<false, false><<<go, 512, SMEM_BIG>>>(out + M_ * D_, p_m2so, p_wos,  D_, D_, D_, D_);
    gemm_tc_kernel<true,  false><<<go, 512, SMEM_BIG>>>(out + M_ * D_, p_sg_o, p_wo2,  D_, D_, D_, D_);
}

// round 8
// speedup vs baseline: 1.7116x; 1.7116x over previous
#include <cuda_runtime.h>
#include <cuda_fp16.h>
#include <math.h>
#include <stdint.h>

// ---------------------------------------------------------------------------
// VDP attention, round 7: all GEMMs fp16 mma.sync.m16n8k16 (2x tf32 rate,
// same 10-bit mantissa => same accuracy). fp16 activations/weights halve
// memory traffic. tcgen05 unavailable (toolchain targets sm_103, not 103a).
// B=4, N=1024, D=1024, H=16, Dh=64.
// ---------------------------------------------------------------------------

#define B_ 4
#define N_ 1024
#define D_ 1024
#define H_ 16
#define DH_ 64
#define M_ (B_ * N_)       /* 4096 rows */
#define QKV_ (3 * D_)      /* 3072 */
#define BH_ (B_ * H_)      /* 64 */
#define SCALE_ 0.125f      /* 64^-0.5 */
#define W_SCALE 4096.0f    /* fp16 range lift for sigma-softmax weights */

// ------------------------- scratch (static device) -------------------------
__device__ __half g_mu_n [M_ * D_];
__device__ __half g_sg_n [M_ * D_];
__device__ __half g_m2s  [M_ * D_];           // mu_n^2 + sigma_n
__device__ __half g_Wq_mu [QKV_ * D_];
__device__ __half g_Wq_sig[QKV_ * D_];
__device__ __half g_Wq_mu2[QKV_ * D_];
__device__ __half g_Wo_mu [D_ * D_];
__device__ __half g_Wo_sig[D_ * D_];
__device__ __half g_Wo_mu2[D_ * D_];
__device__ __half g_mu_qkv[M_ * QKV_];
__device__ __half g_sg_qkv[M_ * QKV_];
__device__ float  g_mu_dots[BH_ * N_ * N_];   // fp32 logits
__device__ float  g_sg_dots[BH_ * N_ * N_];
__device__ __half g_p[BH_ * N_ * N_];         // softmax probs (fp16)
__device__ __half g_w[BH_ * N_ * N_];         // (p(1-p))^2*sg*4096 (fp16)
__device__ __half g_mu_o [M_ * D_];
__device__ __half g_sg_o [M_ * D_];
__device__ __half g_m2s_o[M_ * D_];

// ------------------------------ helpers ------------------------------------
__device__ __forceinline__ void mma_f16(float c[4], const uint32_t a[4],
                                        const uint32_t b[2]) {
    asm volatile(
        "mma.sync.aligned.m16n8k16.row.col.f32.f16.f16.f32 "
        "{%0,%1,%2,%3},{%4,%5,%6,%7},{%8,%9},{%0,%1,%2,%3};"
        : "+f"(c[0]), "+f"(c[1]), "+f"(c[2]), "+f"(c[3])
        : "r"(a[0]), "r"(a[1]), "r"(a[2]), "r"(a[3]), "r"(b[0]), "r"(b[1]));
}

__device__ __forceinline__ void cp16(void* smem_ptr, const void* g) {
    uint32_t s = (uint32_t)__cvta_generic_to_shared(smem_ptr);
    asm volatile("cp.async.cg.shared.global [%0], [%1], 16;\n" :: "r"(s), "l"(g));
}
__device__ __forceinline__ void cp_commit() {
    asm volatile("cp.async.commit_group;\n");
}
template <int N>
__device__ __forceinline__ void cp_wait() {
    asm volatile("cp.async.wait_group %0;\n" :: "n"(N));
}

__device__ __forceinline__ void store2(float* p, float x, float y) {
    *(float2*)p = make_float2(x, y);
}
__device__ __forceinline__ void store2(__half* p, float x, float y) {
    *(__half2*)p = __floats2half2_rn(x, y);
}

// ------------------------- fp16 tensor-core GEMM core ----------------------
// C[M,N] = scale * (A1[M,K1]*B1[N,K1]^T + A2[M,K2]*B2[N,K2]^T), fp32 accum.
// BT=false: B row-major [N,K] (k-contiguous). BT=true: B is [K,N] in gmem
// (n-contiguous), transposed into smem.  BK=32 halfs, 3-stage cp.async.
// Smem pitch 40 halves: verified conflict-free for both STS.128 and frag LDS.
template <typename OT, int THR, int BM, int BN, int WR, int WC, bool BT>
__device__ __forceinline__ void gemm_core16(
    OT* __restrict__ C,
    const __half* __restrict__ A1, const __half* __restrict__ B1,
    const __half* __restrict__ A2, const __half* __restrict__ B2,
    int n1, int n2, int lda, int ldb, int ldc, float scale) {
    constexpr int WM = BM / WR, WN = BN / WC;
    constexpr int MT = WM / 16, NT = WN / 8;
    constexpr int PA = 40;                 // halves
    constexpr int ASZ = BM * PA;
    constexpr int BSZ = BN * PA;
    constexpr int STG = ASZ + BSZ;         // halves per stage
    constexpr int NA  = BM * 4 / THR;      // A cp.async chunks per thread
    constexpr int NB  = BN * 4 / THR;      // B cp.async chunks per thread
    constexpr int NB2 = BN * 16 / THR;     // BT: half2 loads per thread

    extern __shared__ char shraw[];
    __half* sh = (__half*)shraw;

    const int tid = threadIdx.x;
    const int bm = blockIdx.y * BM, bn = blockIdx.x * BN;
    const int w = tid >> 5, lane = tid & 31;
    const int gr = lane >> 2, tc = lane & 3;
    const int wm = (w / WC) * WM, wn = (w % WC) * WN;
    const int niter = n1 + n2;

    auto load_stage = [&](int s, int j) {
        __half* As = sh + s * STG;
        __half* Bs = As + ASZ;
        const __half* Ap; const __half* Bp; int k0;
        if (j < n1) { Ap = A1; Bp = B1; k0 = j * 32; }
        else        { Ap = A2; Bp = B2; k0 = (j - n1) * 32; }
        #pragma unroll
        for (int r = 0; r < NA; r++) {
            int idx = tid + THR * r;
            int row = idx >> 2, c = idx & 3;
            cp16(As + row * PA + c * 8,
                 Ap + (size_t)(bm + row) * lda + k0 + c * 8);
        }
        if (BT) {
            #pragma unroll
            for (int r = 0; r < NB2; r++) {
                int idx = tid + THR * r;
                int kr = idx / (BN / 2), n0 = (idx % (BN / 2)) * 2;
                uint32_t v = *(const uint32_t*)(Bp + (size_t)(k0 + kr) * ldb + bn + n0);
                __half2 h = *(__half2*)&v;
                Bs[n0 * PA + kr]       = __low2half(h);
                Bs[(n0 + 1) * PA + kr] = __high2half(h);
            }
        } else {
            #pragma unroll
            for (int r = 0; r < NB; r++) {
                int idx = tid + THR * r;
                int row = idx >> 2, c = idx & 3;
                cp16(Bs + row * PA + c * 8,
                     Bp + (size_t)(bn + row) * ldb + k0 + c * 8);
            }
        }
    };

    float acc[MT][NT][4] = {};

    load_stage(0, 0);
    cp_commit();
    if (niter > 1) load_stage(1, 1);
    cp_commit();

    for (int i = 0; i < niter; i++) {
        cp_wait<1>();
        __syncthreads();
        if (i + 2 < niter) load_stage((i + 2) % 3, i + 2);
        cp_commit();

        const __half* As = sh + (i % 3) * STG;
        const __half* Bs = As + ASZ;
        #pragma unroll
        for (int g = 0; g < 2; g++) {
            uint32_t af[MT][4], bf[NT][2];
            #pragma unroll
            for (int ii = 0; ii < MT; ii++) {
                int base = (wm + ii * 16 + gr) * PA + g * 16 + 2 * tc;
                af[ii][0] = *(const uint32_t*)(As + base);
                af[ii][1] = *(const uint32_t*)(As + base + 8 * PA);
                af[ii][2] = *(const uint32_t*)(As + base + 8);
                af[ii][3] = *(const uint32_t*)(As + base + 8 * PA + 8);
            }
            #pragma unroll
            for (int j = 0; j < NT; j++) {
                int nb = (wn + j * 8 + gr) * PA + g * 16 + 2 * tc;
                bf[j][0] = *(const uint32_t*)(Bs + nb);
                bf[j][1] = *(const uint32_t*)(Bs + nb + 8);
            }
            #pragma unroll
            for (int ii = 0; ii < MT; ii++)
                #pragma unroll
                for (int j = 0; j < NT; j++)
                    mma_f16(acc[ii][j], af[ii], bf[j]);
        }
        __syncthreads();
    }

    #pragma unroll
    for (int ii = 0; ii < MT; ii++) {
        #pragma unroll
        for (int j = 0; j < NT; j++) {
            int row0 = bm + wm + ii * 16 + gr;
            int col  = bn + wn + j * 8 + 2 * tc;
            OT* p0 = C + (size_t)row0 * ldc + col;
            OT* p1 = C + (size_t)(row0 + 8) * ldc + col;
            store2(p0, acc[ii][j][0] * scale, acc[ii][j][1] * scale);
            store2(p1, acc[ii][j][2] * scale, acc[ii][j][3] * scale);
        }
    }
}

// ---------------------------- kernel wrappers ------------------------------
__global__ void __launch_bounds__(256)
gemm16h_kernel(__half* __restrict__ C,
               const __half* __restrict__ A1, const __half* __restrict__ B1,
               const __half* __restrict__ A2, const __half* __restrict__ B2,
               int n1, int n2, int lda, int ldb, int ldc) {
    gemm_core16<__half, 256, 128, 128, 2, 4, false>(C, A1, B1, A2, B2,
                                                    n1, n2, lda, ldb, ldc, 1.0f);
}

__global__ void __launch_bounds__(256)
gemm16f_kernel(float* __restrict__ C,
               const __half* __restrict__ A1, const __half* __restrict__ B1,
               const __half* __restrict__ A2, const __half* __restrict__ B2,
               int n1, int n2, int lda, int ldb, int ldc) {
    gemm_core16<float, 256, 128, 128, 2, 4, false>(C, A1, B1, A2, B2,
                                                   n1, n2, lda, ldb, ldc, 1.0f);
}

// dots[bh][i][j] = SCALE * sum_d q*k; z>=64 -> sigma path. fp32 output.
__global__ void __launch_bounds__(256)
dots16_kernel() {
    const int z = blockIdx.z;
    const int path = z >> 6, bh = z & 63;
    const __half* qkv = path ? g_sg_qkv : g_mu_qkv;
    float* dots       = path ? g_sg_dots : g_mu_dots;
    const int b = bh >> 4, h = bh & 15;
    const __half* A = qkv + (size_t)b * N_ * QKV_ + h * DH_;
    const __half* K = A + D_;
    float* Cc = dots + (size_t)bh * N_ * N_;
    gemm_core16<float, 256, 128, 128, 2, 4, false>(Cc, A, K, A, K,
                                                   2, 0, QKV_, QKV_, N_, SCALE_);
}

// O[b,i,h*64+d] = sum_j P[bh,i,j] * v[b,j,h,d]; sigma path divides by 4096.
__global__ void __launch_bounds__(256)
pv16_kernel() {
    const int z = blockIdx.z;
    const int path = z >> 6, bh = z & 63;
    const int b = bh >> 4, h = bh & 15;
    const __half* A = (path ? g_w : g_p) + (size_t)bh * N_ * N_;
    const __half* V = (path ? g_sg_qkv : g_mu_qkv)
                      + (size_t)b * N_ * QKV_ + 2 * D_ + h * DH_;
    __half* Cc = (path ? g_sg_o : g_mu_o) + (size_t)b * N_ * D_ + h * DH_;
    gemm_core16<__half, 256, 128, 64, 4, 2, true>(
        Cc, A, V, A, V, 32, 0, N_, QKV_, D_, path ? (1.0f / W_SCALE) : 1.0f);
}

// ------------------------------ prep weights -------------------------------
__device__ __forceinline__ float softplusf(float x) {
    return fmaxf(x, 0.0f) + log1pf(expf(-fabsf(x)));
}

__global__ void prep_weights_kernel(const float* __restrict__ Wqkv_mu,
                                    const float* __restrict__ Wqkv_raw,
                                    const float* __restrict__ Wout_mu,
                                    const float* __restrict__ Wout_raw) {
    int i = blockIdx.x * blockDim.x + threadIdx.x;   // pair index
    const int nq2 = QKV_ * D_ / 2;
    if (i < nq2) {
        int e = 2 * i;
        float w0 = Wqkv_mu[e], w1 = Wqkv_mu[e + 1];
        *(__half2*)(g_Wq_mu  + e) = __floats2half2_rn(w0, w1);
        *(__half2*)(g_Wq_mu2 + e) = __floats2half2_rn(w0 * w0, w1 * w1);
        *(__half2*)(g_Wq_sig + e) = __floats2half2_rn(softplusf(Wqkv_raw[e]),
                                                      softplusf(Wqkv_raw[e + 1]));
    } else {
        int e = 2 * (i - nq2);
        if (e < D_ * D_) {
            float w0 = Wout_mu[e], w1 = Wout_mu[e + 1];
            *(__half2*)(g_Wo_mu  + e) = __floats2half2_rn(w0, w1);
            *(__half2*)(g_Wo_mu2 + e) = __floats2half2_rn(w0 * w0, w1 * w1);
            *(__half2*)(g_Wo_sig + e) = __floats2half2_rn(softplusf(Wout_raw[e]),
                                                          softplusf(Wout_raw[e + 1]));
        }
    }
}

// -------------------------------- layernorm --------------------------------
__global__ void layernorm_kernel(const float* __restrict__ mu,
                                 const float* __restrict__ sigma,
                                 const float* __restrict__ gamma,
                                 const float* __restrict__ beta) {
    const int row = blockIdx.x;
    const int t   = threadIdx.x;
    float4 m = ((const float4*)(mu + (size_t)row * D_))[t];

    float s  = m.x + m.y + m.z + m.w;
    float sq = m.x * m.x + m.y * m.y + m.z * m.z + m.w * m.w;

    __shared__ float red[256];
    red[t] = s; __syncthreads();
    #pragma unroll
    for (int o = 128; o > 0; o >>= 1) { if (t < o) red[t] += red[t + o]; __syncthreads(); }
    float mean = red[0] * (1.0f / D_);
    __syncthreads();
    red[t] = sq; __syncthreads();
    #pragma unroll
    for (int o = 128; o > 0; o >>= 1) { if (t < o) red[t] += red[t + o]; __syncthreads(); }
    float var = red[0] * (1.0f / D_) - mean * mean;
    float inv = rsqrtf(var + 1e-5f);

    const float4 sg = ((const float4*)(sigma + (size_t)row * D_))[t];
    const float4 gm = ((const float4*)gamma)[t];
    const float4 bt = ((const float4*)beta)[t];

    float4 mo, so, m2;
    mo.x = (m.x - mean) * inv * gm.x + bt.x;  so.x = sg.x * gm.x * gm.x * inv * inv;  m2.x = fmaf(mo.x, mo.x, so.x);
    mo.y = (m.y - mean) * inv * gm.y + bt.y;  so.y = sg.y * gm.y * gm.y * inv * inv;  m2.y = fmaf(mo.y, mo.y, so.y);
    mo.z = (m.z - mean) * inv * gm.z + bt.z;  so.z = sg.z * gm.z * gm.z * inv * inv;  m2.z = fmaf(mo.z, mo.z, so.z);
    mo.w = (m.w - mean) * inv * gm.w + bt.w;  so.w = sg.w * gm.w * gm.w * inv * inv;  m2.w = fmaf(mo.w, mo.w, so.w);

    const int e = row * D_ + t * 4;
    *(__half2*)(g_mu_n + e)     = __floats2half2_rn(mo.x, mo.y);
    *(__half2*)(g_mu_n + e + 2) = __floats2half2_rn(mo.z, mo.w);
    *(__half2*)(g_sg_n + e)     = __floats2half2_rn(so.x, so.y);
    *(__half2*)(g_sg_n + e + 2) = __floats2half2_rn(so.z, so.w);
    *(__half2*)(g_m2s + e)      = __floats2half2_rn(m2.x, m2.y);
    *(__half2*)(g_m2s + e + 2)  = __floats2half2_rn(m2.z, m2.w);
}

// --------------------------------- softmax ---------------------------------
// Reads fp32 dots; writes fp16 p and fp16 w = (p(1-p))^2 * sg * 4096.
__global__ void softmax_kernel() {
    const size_t row = blockIdx.x;
    const float* mrow = g_mu_dots + row * N_;
    const float* srow = g_sg_dots + row * N_;
    __half* prow = g_p + row * N_;
    __half* wrow = g_w + row * N_;
    const int t = threadIdx.x;

    float4 m = ((const float4*)mrow)[t];
    float4 sg = ((const float4*)srow)[t];
    float lm = fmaxf(fmaxf(m.x, m.y), fmaxf(m.z, m.w));

    __shared__ float red[256];
    red[t] = lm; __syncthreads();
    #pragma unroll
    for (int o = 128; o > 0; o >>= 1) { if (t < o) red[t] = fmaxf(red[t], red[t + o]); __syncthreads(); }
    const float rmax = red[0];
    __syncthreads();

    float4 e;
    e.x = __expf(m.x - rmax); e.y = __expf(m.y - rmax);
    e.z = __expf(m.z - rmax); e.w = __expf(m.w - rmax);
    red[t] = e.x + e.y + e.z + e.w; __syncthreads();
    #pragma unroll
    for (int o = 128; o > 0; o >>= 1) { if (t < o) red[t] += red[t + o]; __syncthreads(); }
    const float inv = 1.0f / red[0];

    float4 p;
    p.x = e.x * inv; p.y = e.y * inv; p.z = e.z * inv; p.w = e.w * inv;

    float jx = p.x * (1.0f - p.x), jy = p.y * (1.0f - p.y);
    float jz = p.z * (1.0f - p.z), jw = p.w * (1.0f - p.w);
    float wx = jx * jx * sg.x * W_SCALE, wy = jy * jy * sg.y * W_SCALE;
    float wz = jz * jz * sg.z * W_SCALE, ww = jw * jw * sg.w * W_SCALE;

    *(__half2*)(prow + 4 * t)     = __floats2half2_rn(p.x, p.y);
    *(__half2*)(prow + 4 * t + 2) = __floats2half2_rn(p.z, p.w);
    *(__half2*)(wrow + 4 * t)     = __floats2half2_rn(wx, wy);
    *(__half2*)(wrow + 4 * t + 2) = __floats2half2_rn(wz, ww);
}

// ------------------------------ m2s for output -----------------------------
__global__ void m2so_kernel() {
    int i = blockIdx.x * blockDim.x + threadIdx.x;   // half2 index
    __half2 mo = ((const __half2*)g_mu_o)[i];
    __half2 so = ((const __half2*)g_sg_o)[i];
    float2 mf = __half22float2(mo);
    float2 sf = __half22float2(so);
    ((__half2*)g_m2s_o)[i] = __floats2half2_rn(fmaf(mf.x, mf.x, sf.x),
                                               fmaf(mf.y, mf.y, sf.y));
}

// --------------------------------- launch ----------------------------------
extern "C" void kernel_launch(void* const* d_in, const int* in_sizes, int n_in,
                              void* d_out, int out_size) {
    (void)in_sizes; (void)n_in; (void)out_size;
    const float* mu       = (const float*)d_in[0];
    const float* sigma    = (const float*)d_in[1];
    const float* gamma    = (const float*)d_in[2];
    const float* beta     = (const float*)d_in[3];
    const float* Wqkv_mu  = (const float*)d_in[4];
    const float* Wqkv_raw = (const float*)d_in[5];
    const float* Wout_mu  = (const float*)d_in[6];
    const float* Wout_raw = (const float*)d_in[7];
    float* out = (float*)d_out;

    __half *p_mu_n, *p_sg_n, *p_m2s, *p_wq_mu, *p_wq_sig, *p_wq_mu2;
    __half *p_wo_mu, *p_wo_sig, *p_wo_mu2, *p_mu_qkv, *p_sg_qkv;
    __half *p_mu_o, *p_sg_o, *p_m2so;
    cudaGetSymbolAddress((void**)&p_mu_n,   g_mu_n);
    cudaGetSymbolAddress((void**)&p_sg_n,   g_sg_n);
    cudaGetSymbolAddress((void**)&p_m2s,    g_m2s);
    cudaGetSymbolAddress((void**)&p_wq_mu,  g_Wq_mu);
    cudaGetSymbolAddress((void**)&p_wq_sig, g_Wq_sig);
    cudaGetSymbolAddress((void**)&p_wq_mu2, g_Wq_mu2);
    cudaGetSymbolAddress((void**)&p_wo_mu,  g_Wo_mu);
    cudaGetSymbolAddress((void**)&p_wo_sig, g_Wo_sig);
    cudaGetSymbolAddress((void**)&p_wo_mu2, g_Wo_mu2);
    cudaGetSymbolAddress((void**)&p_mu_qkv, g_mu_qkv);
    cudaGetSymbolAddress((void**)&p_sg_qkv, g_sg_qkv);
    cudaGetSymbolAddress((void**)&p_mu_o,   g_mu_o);
    cudaGetSymbolAddress((void**)&p_sg_o,   g_sg_o);
    cudaGetSymbolAddress((void**)&p_m2so,   g_m2s_o);

    const int S_BIG = 3 * (128 * 40 + 128 * 40) * 2;   // 61440 B
    const int S_PV  = 3 * (128 * 40 + 64 * 40) * 2;    // 46080 B
    cudaFuncSetAttribute(gemm16h_kernel, cudaFuncAttributeMaxDynamicSharedMemorySize, S_BIG);
    cudaFuncSetAttribute(gemm16f_kernel, cudaFuncAttributeMaxDynamicSharedMemorySize, S_BIG);
    cudaFuncSetAttribute(dots16_kernel,  cudaFuncAttributeMaxDynamicSharedMemorySize, S_BIG);
    cudaFuncSetAttribute(pv16_kernel,    cudaFuncAttributeMaxDynamicSharedMemorySize, S_PV);

    // 1. weight transforms -> fp16
    prep_weights_kernel<<<(QKV_ * D_ + D_ * D_) / 2 / 256, 256>>>(
        Wqkv_mu, Wqkv_raw, Wout_mu, Wout_raw);

    // 2. layernorm (+ mu^2+sigma) -> fp16
    layernorm_kernel<<<M_, 256>>>(mu, sigma, gamma, beta);

    // 3. QKV projections: mu, then fused sigma (one kernel, K over 2 pairs)
    dim3 gq(QKV_ / 128, M_ / 128);
    gemm16h_kernel<<<gq, 256, S_BIG>>>(p_mu_qkv, p_mu_n, p_wq_mu,
                                       p_mu_n, p_wq_mu, 32, 0, D_, D_, QKV_);
    gemm16h_kernel<<<gq, 256, S_BIG>>>(p_sg_qkv, p_m2s, p_wq_sig,
                                       p_sg_n, p_wq_mu2, 32, 32, D_, D_, QKV_);

    // 4. attention scores (mu & sg), fp32 out, scaled
    dots16_kernel<<<dim3(N_ / 128, N_ / 128, 2 * BH_), 256, S_BIG>>>();

    // 5. softmax + variance Jacobian -> fp16 p, w
    softmax_kernel<<<BH_ * N_, 256>>>();

    // 6. attn @ V (mu & sg) -> fp16 O
    pv16_kernel<<<dim3(1, N_ / 128, 2 * BH_), 256, S_PV>>>();

    // 7. mu_o^2 + sg_o -> fp16
    m2so_kernel<<<(M_ * D_ / 2) / 256, 256>>>();

    // 8. output projection -> fp32 d_out (sigma fused into one kernel)
    dim3 go(D_ / 128, M_ / 128);
    gemm16f_kernel<<<go, 256, S_BIG>>>(out, p_mu_o, p_wo_mu,
                                       p_mu_o, p_wo_mu, 32, 0, D_, D_, D_);
    gemm16f_kernel<<<go, 256, S_BIG>>>(out + M_ * D_, p_m2so, p_wo_sig,
                                       p_sg_o, p_wo_mu2, 32, 32, D_, D_, D_);
}